// round 7
// baseline (speedup 1.0000x reference)
#include <cuda_runtime.h>
#include <math.h>
#include <stdint.h>

// Problem dims
#define BATCH 32
#define EPS   1e-12f

// ---------------- packed global weight layout (per net, 44800 floats) -------
//  w1 : [tap(5)][o(64)][i(68 pad)]   21760   @ 0
//  w2 : [tap(5)][o(64)][i(68 pad)]   21760   @ 21760
//  w0 : [tap(4)][o(64)][i(4)]         1024   @ 43520
//  wo : [o(64)][ch(4)]                 256   @ 44544
#define NET_STRIDE 44800
#define WP_TOTAL   (2 * NET_STRIDE)

__device__ float g_wp[WP_TOTAL];

// ---------------- shared memory layout (floats) -----------------------------
// h arrays have 66 rows: rows 0..63 = pixels, row 64 = permanent ZERO, row 65 = dump
#define SM_W1    0        // 21760
#define SM_W2    21760    // 21760
#define SM_W0    43520    // 1024
#define SM_WO    44544    // 256
#define SM_H0    44800    // 4224  [66][64]
#define SM_H1    49024    // 4224
#define SM_RED1  53248    // 1024  [q 4][a 4][o 64]
#define SM_RED2  54272    // 1024
#define SM_Y     55296    // 264   [66][4]  (row 64 zero, 65 dump)
#define SM_X     55560    // 256   [64px][4ch]
#define SM_LS    55816    // 256
#define SM_B0    56072    // 64
#define SM_B1    56136    // 64
#define SM_B2    56200    // 64
#define SM_BO    56264    // 4
#define SM_MLV   56268    // 32    [buf 2][a 4][ch 4]
#define SM_PART  56300    // 32    [a 4][half 2][ch 4]
#define SM_MBAR  56332    // 2     (56332*4 = 225328, 8B aligned)
#define SMEM_FLOATS 56336
#define SMEM_BYTES  (SMEM_FLOATS * 4)

// Mask-A taps (dr,dc): (-1,-1),(-1,0),(-1,1),(0,-1) ; Mask-B: A + center (0,0)
__global__ void repack_kernel(const float* __restrict__ mw0, const float* __restrict__ mw1,
                              const float* __restrict__ mw2, const float* __restrict__ mwo,
                              const float* __restrict__ lw0, const float* __restrict__ lw1,
                              const float* __restrict__ lw2, const float* __restrict__ lwo)
{
    int t = blockIdx.x * blockDim.x + threadIdx.x;
    if (t >= WP_TOTAL) return;
    const int krA[4] = {0,0,0,1}, kcA[4] = {0,1,2,0};
    const int krB[5] = {0,0,0,1,1}, kcB[5] = {0,1,2,0,1};
    int net = t / NET_STRIDE;
    int u   = t % NET_STRIDE;
    float v;
    if (u < 21760) {                       // w1: [tap][o][68]
        int tap = u / 4352, rem = u % 4352;
        int o = rem / 68, i = rem % 68;
        const float* w = net ? lw1 : mw1;
        v = (i < 64) ? w[((o * 64 + i) * 3 + krB[tap]) * 3 + kcB[tap]] : 0.f;
    } else if (u < 43520) {                // w2
        int u2 = u - 21760;
        int tap = u2 / 4352, rem = u2 % 4352;
        int o = rem / 68, i = rem % 68;
        const float* w = net ? lw2 : mw2;
        v = (i < 64) ? w[((o * 64 + i) * 3 + krB[tap]) * 3 + kcB[tap]] : 0.f;
    } else if (u < 44544) {                // w0: [tap][o][4]
        int u2 = u - 43520;
        int tap = u2 / 256, rem = u2 % 256;
        int o = rem / 4, i = rem % 4;
        const float* w = net ? lw0 : mw0;
        v = w[((o * 4 + i) * 3 + krA[tap]) * 3 + kcA[tap]];
    } else {                               // wo: [o][4]
        int u2 = u - 44544;
        int o = u2 / 4, ch = u2 % 4;
        const float* w = net ? lwo : mwo;
        v = w[ch * 64 + o];
    }
    g_wp[t] = v;
}

__device__ __forceinline__ float elu1(float v) {
    return v > 0.f ? v : (__expf(v) - 1.f);
}

__device__ __forceinline__ uint32_t smem_u32(const void* p) {
    uint32_t a;
    asm("{ .reg .u64 t; cvta.to.shared.u64 t, %1; cvt.u32.u64 %0, t; }" : "=r"(a) : "l"(p));
    return a;
}

__device__ __forceinline__ void st_remote_f32(uint32_t saddr, uint32_t rank, float v) {
    uint32_t raddr;
    asm volatile("mapa.shared::cluster.u32 %0, %1, %2;" : "=r"(raddr) : "r"(saddr), "r"(rank));
    asm volatile("st.shared::cluster.f32 [%0], %1;" :: "r"(raddr), "f"(v) : "memory");
}

__device__ __forceinline__ void arrive_remote(uint32_t mbar_saddr, uint32_t rank) {
    asm volatile(
        "{\n\t"
        ".reg .b32 r;\n\t"
        "mapa.shared::cluster.u32 r, %0, %1;\n\t"
        "mbarrier.arrive.release.cluster.shared::cluster.b64 _, [r];\n\t"
        "}"
        :: "r"(mbar_saddr), "r"(rank) : "memory");
}

__device__ __forceinline__ void mbar_wait(uint32_t mbar_saddr, uint32_t parity) {
    asm volatile(
        "{\n\t"
        ".reg .pred P1;\n\t"
        "WAIT_LOOP_%=:\n\t"
        "mbarrier.try_wait.parity.acquire.cluster.shared::cta.b64 P1, [%0], %1, 0x989680;\n\t"
        "@P1 bra.uni WAIT_DONE_%=;\n\t"
        "bra.uni WAIT_LOOP_%=;\n\t"
        "WAIT_DONE_%=:\n\t"
        "}"
        :: "r"(mbar_saddr), "r"(parity) : "memory");
}

__device__ __forceinline__ void ffma2(unsigned long long& acc, unsigned long long w,
                                      unsigned long long h) {
    asm("fma.rn.f32x2 %0, %1, %2, %0;" : "+l"(acc) : "l"(w), "l"(h));
}

__device__ __forceinline__ float f2sum(unsigned long long v) {
    return __uint_as_float((uint32_t)v) + __uint_as_float((uint32_t)(v >> 32));
}

__global__ void __cluster_dims__(2, 1, 1) __launch_bounds__(512, 1)
made_kernel(const float* __restrict__ x,
            const float* __restrict__ mb0, const float* __restrict__ mb1,
            const float* __restrict__ mb2, const float* __restrict__ mbo,
            const float* __restrict__ lb0, const float* __restrict__ lb1,
            const float* __restrict__ lb2, const float* __restrict__ lbo,
            float* __restrict__ out)
{
    extern __shared__ float sm[];
    const int tid = threadIdx.x;
    const int b = blockIdx.x >> 1;
    uint32_t net;
    asm("mov.u32 %0, %%cluster_ctarank;" : "=r"(net));
    const uint32_t peer = net ^ 1u;
    const uint32_t smbase = smem_u32(sm);
    const uint32_t mbar = smbase + SM_MBAR * 4u;

    // ---- startup: weights + state into smem ----
    {
        const float4* src = (const float4*)(g_wp + net * NET_STRIDE);
        float4* dst = (float4*)sm;
        #pragma unroll 4
        for (int i = tid; i < NET_STRIDE / 4; i += 512)
            dst[i] = src[i];
    }
    if (tid < 264) sm[SM_Y + tid] = 0.f;      // all y rows zero (incl. sentinel row)
    if (tid < 256) {
        int ch = tid >> 6, p = tid & 63;
        sm[SM_X + p * 4 + ch] = x[b * 256 + tid];
    }
    if (tid < 128) {                           // zero sentinel rows 64 of h0/h1
        sm[SM_H0 + 64 * 64 + (tid & 63)] = 0.f;
        sm[SM_H1 + 64 * 64 + (tid & 63)] = 0.f;
    }
    if (tid < 64) {
        sm[SM_B0 + tid] = net ? lb0[tid] : mb0[tid];
        sm[SM_B1 + tid] = net ? lb1[tid] : mb1[tid];
        sm[SM_B2 + tid] = net ? lb2[tid] : mb2[tid];
    }
    if (tid < 4) sm[SM_BO + tid] = net ? lbo[tid] : mbo[tid];
    if (tid == 0)
        asm volatile("mbarrier.init.shared.b64 [%0], %1;" :: "r"(mbar), "r"(16) : "memory");
    __syncthreads();
    asm volatile("barrier.cluster.arrive.aligned;" ::: "memory");
    asm volatile("barrier.cluster.wait.aligned;" ::: "memory");

    const int dR[4] = {-1,-1,-1, 0}, dC[4] = {-1, 0, 1,-1};  // non-center taps

    const int t8  = tid & 255;
    const int grp = tid >> 8;        // 0: L0 + GEMM1nc, 1: GEMM2nc
    const int o   = t8 & 63;
    const int q   = t8 >> 6;         // i-quarter (16 floats) in P1; a-slot in P2/P3

    #pragma unroll 1
    for (int s = 0; s < 22; s++) {
        int rlo = (s - 6) > 0 ? (s - 6) / 2 : 0;
        int rhi = (s >> 1) < 7 ? (s >> 1) : 7;
        int npix = rhi - rlo + 1;

        // uniform per-step index tables (sentinel 64 = zero row, 65 = dump row)
        int ptB[4][4];     // [tap][a] read row (h0 for GEMM1nc / h1 for GEMM2nc)
        int pa_r[4];       // center read row
        int pa_w[4];       // center/store write row
        int pa_real[4];    // actual pixel index (valid a only)
        #pragma unroll
        for (int a = 0; a < 4; a++) {
            int ra_ = rlo + a, ca_ = s - 2 * ra_;
            int p = ra_ * 8 + ca_;
            bool va = (a < npix);
            pa_real[a] = p;
            pa_r[a] = va ? p : 64;
            pa_w[a] = va ? p : 65;
            #pragma unroll
            for (int tap = 0; tap < 4; tap++) {
                int rr = ra_ + dR[tap], cc = ca_ + dC[tap];
                ptB[tap][a] = (va && rr >= 0 && cc >= 0 && cc < 8) ? rr * 8 + cc : 64;
            }
        }

        // ======== P1 ========
        if (grp == 0) {
            // ---- L0 (mask A, 4 -> 64): thread (o, slot q) — branch-free via sentinels
            {
                float acc = sm[SM_B0 + o];
                #pragma unroll
                for (int tap = 0; tap < 4; tap++) {
                    float4 w  = *(const float4*)(sm + SM_W0 + (tap * 64 + o) * 4);
                    float4 y4 = *(const float4*)(sm + SM_Y + ptB[tap][q] * 4);
                    acc += w.x * y4.x + w.y * y4.y + w.z * y4.z + w.w * y4.w;
                }
                sm[SM_H0 + pa_w[q] * 64 + o] = elu1(acc);
            }
            // ---- GEMM1 non-center partials, f32x2, straight-line ----
            {
                unsigned long long a0 = 0, a1 = 0, a2 = 0, a3 = 0;
                const float* wbase = sm + SM_W1 + o * 68 + q * 16;
                #pragma unroll
                for (int tap = 0; tap < 4; tap++) {
                    const ulonglong2* wp = (const ulonglong2*)(wbase + tap * 4352);
                    ulonglong2 wA = wp[0], wB = wp[1], wC = wp[2], wD = wp[3];
                    #pragma unroll
                    for (int a = 0; a < 4; a++) {
                        const ulonglong2* hp =
                            (const ulonglong2*)(sm + SM_H0 + ptB[tap][a] * 64 + q * 16);
                        ulonglong2 hA = hp[0], hB = hp[1], hC = hp[2], hD = hp[3];
                        unsigned long long* acc = (a == 0) ? &a0 : (a == 1) ? &a1 : (a == 2) ? &a2 : &a3;
                        ffma2(*acc, wA.x, hA.x); ffma2(*acc, wA.y, hA.y);
                        ffma2(*acc, wB.x, hB.x); ffma2(*acc, wB.y, hB.y);
                        ffma2(*acc, wC.x, hC.x); ffma2(*acc, wC.y, hC.y);
                        ffma2(*acc, wD.x, hD.x); ffma2(*acc, wD.y, hD.y);
                    }
                }
                float* rb = sm + SM_RED1 + q * 256 + o;
                rb[0]   = f2sum(a0);
                rb[64]  = f2sum(a1);
                rb[128] = f2sum(a2);
                rb[192] = f2sum(a3);
            }
        } else {
            // ---- GEMM2 non-center partials on h1 (older diagonals) ----
            unsigned long long a0 = 0, a1 = 0, a2 = 0, a3 = 0;
            const float* wbase = sm + SM_W2 + o * 68 + q * 16;
            #pragma unroll
            for (int tap = 0; tap < 4; tap++) {
                const ulonglong2* wp = (const ulonglong2*)(wbase + tap * 4352);
                ulonglong2 wA = wp[0], wB = wp[1], wC = wp[2], wD = wp[3];
                #pragma unroll
                for (int a = 0; a < 4; a++) {
                    const ulonglong2* hp =
                        (const ulonglong2*)(sm + SM_H1 + ptB[tap][a] * 64 + q * 16);
                    ulonglong2 hA = hp[0], hB = hp[1], hC = hp[2], hD = hp[3];
                    unsigned long long* acc = (a == 0) ? &a0 : (a == 1) ? &a1 : (a == 2) ? &a2 : &a3;
                    ffma2(*acc, wA.x, hA.x); ffma2(*acc, wA.y, hA.y);
                    ffma2(*acc, wB.x, hB.x); ffma2(*acc, wB.y, hB.y);
                    ffma2(*acc, wC.x, hC.x); ffma2(*acc, wC.y, hC.y);
                    ffma2(*acc, wD.x, hD.x); ffma2(*acc, wD.y, hD.y);
                }
            }
            float* rb = sm + SM_RED2 + q * 256 + o;
            rb[0]   = f2sum(a0);
            rb[64]  = f2sum(a1);
            rb[128] = f2sum(a2);
            rb[192] = f2sum(a3);
        }
        __syncthreads();

        // ======== P2: GEMM1 center tap (full 64 i) + combine -> h1 (256 thr) ========
        if (tid < 256) {
            unsigned long long acc = 0;
            const ulonglong2* wp = (const ulonglong2*)(sm + SM_W1 + (256 + o) * 68);
            const ulonglong2* hp = (const ulonglong2*)(sm + SM_H0 + pa_r[q] * 64);
            #pragma unroll
            for (int k = 0; k < 16; k++) {     // 16 x ulonglong2 = 64 floats
                ulonglong2 w = wp[k], h = hp[k];
                ffma2(acc, w.x, h.x);
                ffma2(acc, w.y, h.y);
            }
            float v = f2sum(acc) + sm[SM_B1 + o]
                    + sm[SM_RED1 +   0 + q * 64 + o]
                    + sm[SM_RED1 + 256 + q * 64 + o]
                    + sm[SM_RED1 + 512 + q * 64 + o]
                    + sm[SM_RED1 + 768 + q * 64 + o];
            sm[SM_H1 + pa_w[q] * 64 + o] = elu1(v);
        }
        __syncthreads();

        // ======== P3: GEMM2 center tap (full 64 i) + combine + out conv (256 thr) ==
        if (tid < 256) {
            unsigned long long acc = 0;
            const ulonglong2* wp = (const ulonglong2*)(sm + SM_W2 + (256 + o) * 68);
            const ulonglong2* hp = (const ulonglong2*)(sm + SM_H1 + pa_r[q] * 64);
            #pragma unroll
            for (int k = 0; k < 16; k++) {     // 16 x ulonglong2 = 64 floats
                ulonglong2 w = wp[k], h = hp[k];
                ffma2(acc, w.x, h.x);
                ffma2(acc, w.y, h.y);
            }
            float v = f2sum(acc) + sm[SM_B2 + o]
                    + sm[SM_RED2 +   0 + q * 64 + o]
                    + sm[SM_RED2 + 256 + q * 64 + o]
                    + sm[SM_RED2 + 512 + q * 64 + o]
                    + sm[SM_RED2 + 768 + q * 64 + o];
            v = elu1(v);
            float4 wo4 = *(const float4*)(sm + SM_WO + o * 4);
            float c0 = v * wo4.x, c1 = v * wo4.y, c2 = v * wo4.z, c3 = v * wo4.w;
            #pragma unroll
            for (int off = 16; off >= 1; off >>= 1) {
                c0 += __shfl_down_sync(0xffffffffu, c0, off);
                c1 += __shfl_down_sync(0xffffffffu, c1, off);
                c2 += __shfl_down_sync(0xffffffffu, c2, off);
                c3 += __shfl_down_sync(0xffffffffu, c3, off);
            }
            if (q < npix && (tid & 31) == 0) {
                int half = (tid >> 5) & 1;
                float* pp = sm + SM_PART + (q * 2 + half) * 4;
                pp[0] = c0; pp[1] = c1; pp[2] = c2; pp[3] = c3;
            }
        }
        __syncthreads();

        // ======== P4: finalize + peer exchange + y update (16 thr) ========
        int buf = s & 1;
        if (tid < 16) {
            int a = tid >> 2, ch = tid & 3;
            float v = 0.f;
            if (a < npix) {
                v = sm[SM_PART + (a * 2 + 0) * 4 + ch]
                  + sm[SM_PART + (a * 2 + 1) * 4 + ch]
                  + sm[SM_BO + ch];
                uint32_t off = (uint32_t)(SM_MLV + buf * 16 + a * 4 + ch) * 4u;
                st_remote_f32(smbase + off, peer, v);
            }
            arrive_remote(mbar, peer);
            mbar_wait(mbar, (uint32_t)(s & 1));
            if (a < npix) {
                float pv = sm[SM_MLV + buf * 16 + a * 4 + ch];
                float mu = net ? pv : v;
                float ls = 0.5f * (net ? v : pv);
                int p = pa_real[a];
                float yv = (sm[SM_X + p * 4 + ch] - mu) / (__expf(ls) + EPS);
                sm[SM_Y + p * 4 + ch] = yv;
                sm[SM_LS + p * 4 + ch] = ls;
            }
        }
        __syncthreads();
    }

    // ---- outputs ----
    if (net == 0) {
        if (tid < 256)
            out[b * 256 + tid] = sm[SM_Y + (tid & 63) * 4 + (tid >> 6)];
    } else {
        if (tid < 32) {
            float a = 0.f;
            #pragma unroll
            for (int k = 0; k < 8; k++) a += sm[SM_LS + tid * 8 + k];
            #pragma unroll
            for (int off = 16; off >= 1; off >>= 1)
                a += __shfl_down_sync(0xffffffffu, a, off);
            if (tid == 0) out[BATCH * 256 + b] = a;
        }
    }

    asm volatile("barrier.cluster.arrive.aligned;" ::: "memory");
    asm volatile("barrier.cluster.wait.aligned;" ::: "memory");
}

extern "C" void kernel_launch(void* const* d_in, const int* in_sizes, int n_in,
                              void* d_out, int out_size)
{
    (void)in_sizes; (void)n_in; (void)out_size;
    const float* x   = (const float*)d_in[0];
    const float* mw0 = (const float*)d_in[1];
    const float* mb0 = (const float*)d_in[2];
    const float* mw1 = (const float*)d_in[3];
    const float* mb1 = (const float*)d_in[4];
    const float* mw2 = (const float*)d_in[5];
    const float* mb2 = (const float*)d_in[6];
    const float* mwo = (const float*)d_in[7];
    const float* mbo = (const float*)d_in[8];
    const float* lw0 = (const float*)d_in[9];
    const float* lb0 = (const float*)d_in[10];
    const float* lw1 = (const float*)d_in[11];
    const float* lb1 = (const float*)d_in[12];
    const float* lw2 = (const float*)d_in[13];
    const float* lb2 = (const float*)d_in[14];
    const float* lwo = (const float*)d_in[15];
    const float* lbo = (const float*)d_in[16];
    float* out = (float*)d_out;

    cudaFuncSetAttribute(made_kernel, cudaFuncAttributeMaxDynamicSharedMemorySize, SMEM_BYTES);

    repack_kernel<<<(WP_TOTAL + 255) / 256, 256>>>(mw0, mw1, mw2, mwo, lw0, lw1, lw2, lwo);
    made_kernel<<<2 * BATCH, 512, SMEM_BYTES>>>(x, mb0, mb1, mb2, mbo,
                                                lb0, lb1, lb2, lbo, out);
}

// round 8
// speedup vs baseline: 1.0941x; 1.0941x over previous
#include <cuda_runtime.h>
#include <math.h>
#include <stdint.h>

// Problem dims
#define BATCH 32
#define EPS   1e-12f

// ---------------- packed global weight layout (per net, 44800 floats) -------
//  w1 : [tap(5)][o(64)][i(68 pad)]   21760   @ 0
//  w2 : [tap(5)][o(64)][i(68 pad)]   21760   @ 21760
//  w0 : [tap(4)][o(64)][i(4)]         1024   @ 43520
//  wo : [o(64)][ch(4)]                 256   @ 44544
#define NET_STRIDE 44800
#define WP_TOTAL   (2 * NET_STRIDE)

__device__ float g_wp[WP_TOTAL];

// ---------------- shared memory layout (floats), per CTA = (net, o-half) ----
#define SM_W1s   0        // 5*32*68 = 10880   [tap][o32][68]
#define SM_W2s   10880    // 10880
#define SM_W0s   21760    // 4*32*4 = 512      [tap][o32][4]
#define SM_WOs   22272    // 128               [o32][4]
#define SM_H0    22400    // 4096  [64px][64]  (full width, halves exchanged)
#define SM_H1    26496    // 4096
#define SM_RED1  30592    // 512   [q4][a4][o32]
#define SM_RED2  31104    // 512
#define SM_Y     31616    // 256   [64px][4ch]
#define SM_X     31872    // 256
#define SM_LS    32128    // 256
#define SM_B0s   32384    // 32
#define SM_B1s   32416    // 32
#define SM_B2s   32448    // 32
#define SM_BOh   32480    // 4     (my net's output bias; added by half==0 only)
#define SM_MLV   32484    // 128   [buf2][rank4][a4][ch4]
#define SM_PART  32612    // 32    [a4][whalf2][ch4]
#define SM_MB_H0 32644    // 2  (32644*4 % 8 == 0)
#define SM_MB_H1 32646    // 2
#define SM_MB_P4 32648    // 2
#define SMEM_FLOATS 32656
#define SMEM_BYTES  (SMEM_FLOATS * 4)

// Mask-A taps (dr,dc): (-1,-1),(-1,0),(-1,1),(0,-1) ; Mask-B: A + center (0,0)
__global__ void repack_kernel(const float* __restrict__ mw0, const float* __restrict__ mw1,
                              const float* __restrict__ mw2, const float* __restrict__ mwo,
                              const float* __restrict__ lw0, const float* __restrict__ lw1,
                              const float* __restrict__ lw2, const float* __restrict__ lwo)
{
    int t = blockIdx.x * blockDim.x + threadIdx.x;
    if (t >= WP_TOTAL) return;
    const int krA[4] = {0,0,0,1}, kcA[4] = {0,1,2,0};
    const int krB[5] = {0,0,0,1,1}, kcB[5] = {0,1,2,0,1};
    int net = t / NET_STRIDE;
    int u   = t % NET_STRIDE;
    float v;
    if (u < 21760) {                       // w1: [tap][o][68]
        int tap = u / 4352, rem = u % 4352;
        int o = rem / 68, i = rem % 68;
        const float* w = net ? lw1 : mw1;
        v = (i < 64) ? w[((o * 64 + i) * 3 + krB[tap]) * 3 + kcB[tap]] : 0.f;
    } else if (u < 43520) {                // w2
        int u2 = u - 21760;
        int tap = u2 / 4352, rem = u2 % 4352;
        int o = rem / 68, i = rem % 68;
        const float* w = net ? lw2 : mw2;
        v = (i < 64) ? w[((o * 64 + i) * 3 + krB[tap]) * 3 + kcB[tap]] : 0.f;
    } else if (u < 44544) {                // w0: [tap][o][4]
        int u2 = u - 43520;
        int tap = u2 / 256, rem = u2 % 256;
        int o = rem / 4, i = rem % 4;
        const float* w = net ? lw0 : mw0;
        v = w[((o * 4 + i) * 3 + krA[tap]) * 3 + kcA[tap]];
    } else {                               // wo: [o][4]
        int u2 = u - 44544;
        int o = u2 / 4, ch = u2 % 4;
        const float* w = net ? lwo : mwo;
        v = w[ch * 64 + o];
    }
    g_wp[t] = v;
}

__device__ __forceinline__ float elu1(float v) {
    return v > 0.f ? v : (__expf(v) - 1.f);
}

__device__ __forceinline__ uint32_t smem_u32(const void* p) {
    uint32_t a;
    asm("{ .reg .u64 t; cvta.to.shared.u64 t, %1; cvt.u32.u64 %0, t; }" : "=r"(a) : "l"(p));
    return a;
}

__device__ __forceinline__ void st_remote_f32(uint32_t saddr, uint32_t rank, float v) {
    uint32_t raddr;
    asm volatile("mapa.shared::cluster.u32 %0, %1, %2;" : "=r"(raddr) : "r"(saddr), "r"(rank));
    asm volatile("st.shared::cluster.f32 [%0], %1;" :: "r"(raddr), "f"(v) : "memory");
}

__device__ __forceinline__ void arrive_remote(uint32_t mbar_saddr, uint32_t rank) {
    asm volatile(
        "{\n\t"
        ".reg .b32 r;\n\t"
        "mapa.shared::cluster.u32 r, %0, %1;\n\t"
        "mbarrier.arrive.release.cluster.shared::cluster.b64 _, [r];\n\t"
        "}"
        :: "r"(mbar_saddr), "r"(rank) : "memory");
}

__device__ __forceinline__ void mbar_wait(uint32_t mbar_saddr, uint32_t parity) {
    asm volatile(
        "{\n\t"
        ".reg .pred P1;\n\t"
        "WAIT_LOOP_%=:\n\t"
        "mbarrier.try_wait.parity.acquire.cluster.shared::cta.b64 P1, [%0], %1, 0x989680;\n\t"
        "@P1 bra.uni WAIT_DONE_%=;\n\t"
        "bra.uni WAIT_LOOP_%=;\n\t"
        "WAIT_DONE_%=:\n\t"
        "}"
        :: "r"(mbar_saddr), "r"(parity) : "memory");
}

__global__ void __cluster_dims__(4, 1, 1) __launch_bounds__(512, 1)
made_kernel(const float* __restrict__ x,
            const float* __restrict__ mb0, const float* __restrict__ mb1,
            const float* __restrict__ mb2, const float* __restrict__ mbo,
            const float* __restrict__ lb0, const float* __restrict__ lb1,
            const float* __restrict__ lb2, const float* __restrict__ lbo,
            float* __restrict__ out)
{
    extern __shared__ float sm[];
    const int tid = threadIdx.x;
    const int b = blockIdx.x >> 2;
    uint32_t rank;
    asm("mov.u32 %0, %%cluster_ctarank;" : "=r"(rank));
    const int net  = (int)(rank >> 1);
    const int half = (int)(rank & 1);
    const uint32_t hpeer = rank ^ 1u;      // same net, other o-half
    const uint32_t smbase = smem_u32(sm);
    const uint32_t mb_h0 = smbase + SM_MB_H0 * 4u;
    const uint32_t mb_h1 = smbase + SM_MB_H1 * 4u;
    const uint32_t mb_p4 = smbase + SM_MB_P4 * 4u;

    // ---- startup: weight slices + state ----
    {
        const float* gw = g_wp + net * NET_STRIDE;
        // W1s/W2s slices: per tap, 32 rows of 68 = 2176 floats (544 float4)
        for (int idx = tid; idx < 2 * 5 * 544; idx += 512) {
            int lay = idx / 2720, rem = idx % 2720;
            int tap = rem / 544, f4 = rem % 544;
            const float4* src = (const float4*)(gw + (lay ? 21760 : 0) +
                                                (tap * 64 + half * 32) * 68) + f4;
            float4* dst = (float4*)(sm + (lay ? SM_W2s : SM_W1s) + tap * 2176) + f4;
            *dst = *src;
        }
        if (tid < 512) {
            // W0s: [tap4][o32][4]
            int tap = tid >> 7, within = tid & 127;
            sm[SM_W0s + tid] = gw[43520 + tap * 256 + half * 128 + within];
        }
        if (tid < 128) sm[SM_WOs + tid] = gw[44544 + half * 128 + tid];
        if (tid < 256) {
            int ch = tid >> 6, p = tid & 63;
            sm[SM_X + p * 4 + ch] = x[b * 256 + tid];
            sm[SM_Y + tid] = 0.f;
        }
        if (tid < 32) {
            sm[SM_B0s + tid] = (net ? lb0 : mb0)[half * 32 + tid];
            sm[SM_B1s + tid] = (net ? lb1 : mb1)[half * 32 + tid];
            sm[SM_B2s + tid] = (net ? lb2 : mb2)[half * 32 + tid];
        }
        if (tid < 4) sm[SM_BOh + tid] = (net ? lbo : mbo)[tid];
        if (tid == 0) {
            asm volatile("mbarrier.init.shared.b64 [%0], %1;" :: "r"(mb_h0), "r"(128) : "memory");
            asm volatile("mbarrier.init.shared.b64 [%0], %1;" :: "r"(mb_h1), "r"(256) : "memory");
            asm volatile("mbarrier.init.shared.b64 [%0], %1;" :: "r"(mb_p4), "r"(48)  : "memory");
        }
    }
    __syncthreads();
    asm volatile("barrier.cluster.arrive.aligned;" ::: "memory");
    asm volatile("barrier.cluster.wait.aligned;" ::: "memory");

    const int dRA[4] = {-1,-1,-1, 0}, dCA[4] = {-1, 0, 1,-1};   // mask-A / non-center B taps

    #pragma unroll 1
    for (int s = 0; s < 22; s++) {
        int rlo = (s - 6) > 0 ? (s - 6) / 2 : 0;
        int rhi = (s >> 1) < 7 ? (s >> 1) : 7;
        int npix = rhi - rlo + 1;
        uint32_t parity = (uint32_t)(s & 1);
        int buf = s & 1;

        int ra[4], ca[4], pa[4];
        #pragma unroll
        for (int a = 0; a < 4; a++) {
            ra[a] = rlo + a;
            ca[a] = s - 2 * ra[a];
            pa[a] = ra[a] * 8 + ca[a];
        }

        // ======== Phase A ========
        // L0 (my o-half) + immediate push to same-net peer
        if (tid < 128) {
            int o = tid & 31, a = tid >> 5;
            if (a < npix) {
                float acc = sm[SM_B0s + o];
                #pragma unroll
                for (int tap = 0; tap < 4; tap++) {
                    int rr = ra[a] + dRA[tap], cc = ca[a] + dCA[tap];
                    if (rr >= 0 && cc >= 0 && cc < 8) {
                        float4 w  = *(const float4*)(sm + SM_W0s + (tap * 32 + o) * 4);
                        float4 y4 = *(const float4*)(sm + SM_Y + (rr * 8 + cc) * 4);
                        acc += w.x * y4.x + w.y * y4.y + w.z * y4.z + w.w * y4.w;
                    }
                }
                float h = elu1(acc);
                int off = SM_H0 + pa[a] * 64 + half * 32 + o;
                sm[off] = h;
                st_remote_f32(smbase + (uint32_t)off * 4u, hpeer, h);
            }
            arrive_remote(mb_h0, hpeer);
        }
        // non-center GEMM partials (reads only older diagonals) — hides h0 exchange
        {
            int lay  = tid >> 8;            // 0: GEMM1nc (h0), 1: GEMM2nc (h1)
            int rest = tid & 255;
            int asub = rest >> 7;           // handles a = 2*asub, 2*asub+1
            int q    = (rest >> 5) & 3;     // 16-float i-quarter
            int o    = rest & 31;
            const float* W = sm + (lay ? SM_W2s : SM_W1s);
            const float* H = sm + (lay ? SM_H1 : SM_H0);
            float* RED = sm + (lay ? SM_RED2 : SM_RED1);
            int a0 = asub * 2, a1 = a0 + 1;
            float acc0 = 0.f, acc1 = 0.f;
            #pragma unroll
            for (int tap = 0; tap < 4; tap++) {
                const float4* wr = (const float4*)(W + (tap * 32 + o) * 68 + q * 16);
                float4 w0 = wr[0], w1 = wr[1], w2 = wr[2], w3 = wr[3];
                {
                    int rr = ra[a0] + dRA[tap], cc = ca[a0] + dCA[tap];
                    if (a0 < npix && rr >= 0 && cc >= 0 && cc < 8) {
                        const float4* hp = (const float4*)(H + (rr * 8 + cc) * 64 + q * 16);
                        float4 h0 = hp[0], h1 = hp[1], h2 = hp[2], h3 = hp[3];
                        acc0 += w0.x*h0.x + w0.y*h0.y + w0.z*h0.z + w0.w*h0.w
                              + w1.x*h1.x + w1.y*h1.y + w1.z*h1.z + w1.w*h1.w
                              + w2.x*h2.x + w2.y*h2.y + w2.z*h2.z + w2.w*h2.w
                              + w3.x*h3.x + w3.y*h3.y + w3.z*h3.z + w3.w*h3.w;
                    }
                }
                {
                    int rr = ra[a1] + dRA[tap], cc = ca[a1] + dCA[tap];
                    if (a1 < npix && rr >= 0 && cc >= 0 && cc < 8) {
                        const float4* hp = (const float4*)(H + (rr * 8 + cc) * 64 + q * 16);
                        float4 h0 = hp[0], h1 = hp[1], h2 = hp[2], h3 = hp[3];
                        acc1 += w0.x*h0.x + w0.y*h0.y + w0.z*h0.z + w0.w*h0.w
                              + w1.x*h1.x + w1.y*h1.y + w1.z*h1.z + w1.w*h1.w
                              + w2.x*h2.x + w2.y*h2.y + w2.z*h2.z + w2.w*h2.w
                              + w3.x*h3.x + w3.y*h3.y + w3.z*h3.z + w3.w*h3.w;
                    }
                }
            }
            RED[(q * 4 + a0) * 32 + o] = acc0;
            RED[(q * 4 + a1) * 32 + o] = acc1;
        }
        mbar_wait(mb_h0, parity);
        __syncthreads();

        // ======== Phase B: center1 over full h0 -> my h1 half, push ========
        if (tid < 256) {
            int ih = tid & 1, o = (tid >> 1) & 31, a = tid >> 6;
            float v = 0.f;
            if (a < npix) {
                const float4* wr = (const float4*)(sm + SM_W1s + (128 + o) * 68 + ih * 32);
                const float4* hp = (const float4*)(sm + SM_H0 + pa[a] * 64 + ih * 32);
                #pragma unroll
                for (int k = 0; k < 8; k++) {
                    float4 w = wr[k], h = hp[k];
                    v += w.x*h.x + w.y*h.y + w.z*h.z + w.w*h.w;
                }
            }
            v += __shfl_down_sync(0xffffffffu, v, 1);
            if (a < npix && ih == 0) {
                v += sm[SM_B1s + o]
                   + sm[SM_RED1 + (0 * 4 + a) * 32 + o]
                   + sm[SM_RED1 + (1 * 4 + a) * 32 + o]
                   + sm[SM_RED1 + (2 * 4 + a) * 32 + o]
                   + sm[SM_RED1 + (3 * 4 + a) * 32 + o];
                float h = elu1(v);
                int off = SM_H1 + pa[a] * 64 + half * 32 + o;
                sm[off] = h;
                st_remote_f32(smbase + (uint32_t)off * 4u, hpeer, h);
            }
            arrive_remote(mb_h1, hpeer);
        }
        mbar_wait(mb_h1, parity);
        __syncthreads();

        // ======== Phase C: center2 + combine + out-conv partials ========
        if (tid < 256) {
            int ih = tid & 1, o = (tid >> 1) & 31, a = tid >> 6;
            float v = 0.f;
            if (a < npix) {
                const float4* wr = (const float4*)(sm + SM_W2s + (128 + o) * 68 + ih * 32);
                const float4* hp = (const float4*)(sm + SM_H1 + pa[a] * 64 + ih * 32);
                #pragma unroll
                for (int k = 0; k < 8; k++) {
                    float4 w = wr[k], h = hp[k];
                    v += w.x*h.x + w.y*h.y + w.z*h.z + w.w*h.w;
                }
            }
            v += __shfl_down_sync(0xffffffffu, v, 1);
            float c0 = 0.f, c1 = 0.f, c2 = 0.f, c3 = 0.f;
            if (a < npix && ih == 0) {
                v += sm[SM_B2s + o]
                   + sm[SM_RED2 + (0 * 4 + a) * 32 + o]
                   + sm[SM_RED2 + (1 * 4 + a) * 32 + o]
                   + sm[SM_RED2 + (2 * 4 + a) * 32 + o]
                   + sm[SM_RED2 + (3 * 4 + a) * 32 + o];
                v = elu1(v);
                float4 wo4 = *(const float4*)(sm + SM_WOs + o * 4);
                c0 = v * wo4.x; c1 = v * wo4.y; c2 = v * wo4.z; c3 = v * wo4.w;
            }
            // sum over the warp's 16 o's (data at even lanes; zeros elsewhere)
            #pragma unroll
            for (int off = 16; off >= 2; off >>= 1) {
                c0 += __shfl_down_sync(0xffffffffu, c0, off);
                c1 += __shfl_down_sync(0xffffffffu, c1, off);
                c2 += __shfl_down_sync(0xffffffffu, c2, off);
                c3 += __shfl_down_sync(0xffffffffu, c3, off);
            }
            if ((tid & 31) == 0) {
                int wh = (tid >> 5) & 1;   // warp = a*2 + wh
                float* pp = sm + SM_PART + (a * 2 + wh) * 4;
                pp[0] = c0; pp[1] = c1; pp[2] = c2; pp[3] = c3;
            }
        }
        __syncthreads();

        // ======== Phase D: 4-way exchange + y update (16 thr) ========
        if (tid < 16) {
            int a = tid >> 2, ch = tid & 3;
            if (a < npix) {
                float v = sm[SM_PART + (a * 2 + 0) * 4 + ch]
                        + sm[SM_PART + (a * 2 + 1) * 4 + ch];
                if (half == 0) v += sm[SM_BOh + ch];
                uint32_t off = (uint32_t)(SM_MLV + buf * 64 + (int)rank * 16 + a * 4 + ch) * 4u;
                sm[SM_MLV + buf * 64 + (int)rank * 16 + a * 4 + ch] = v;
                #pragma unroll
                for (int pr = 0; pr < 4; pr++)
                    if (pr != (int)rank)
                        st_remote_f32(smbase + off, (uint32_t)pr, v);
            }
            #pragma unroll
            for (int pr = 0; pr < 4; pr++)
                if (pr != (int)rank)
                    arrive_remote(mb_p4, (uint32_t)pr);
            mbar_wait(mb_p4, parity);
            if (a < npix) {
                const float* mlv = sm + SM_MLV + buf * 64;
                float mu = mlv[0 * 16 + a * 4 + ch] + mlv[1 * 16 + a * 4 + ch];
                float lv = mlv[2 * 16 + a * 4 + ch] + mlv[3 * 16 + a * 4 + ch];
                float ls = 0.5f * lv;
                int p = pa[a];
                float yv = (sm[SM_X + p * 4 + ch] - mu) / (__expf(ls) + EPS);
                sm[SM_Y + p * 4 + ch] = yv;
                sm[SM_LS + p * 4 + ch] = ls;
            }
        }
        __syncthreads();
    }

    // ---- outputs ----
    if (rank == 0) {
        if (tid < 256)
            out[b * 256 + tid] = sm[SM_Y + (tid & 63) * 4 + (tid >> 6)];
    } else if (rank == 2) {
        if (tid < 32) {
            float a = 0.f;
            #pragma unroll
            for (int k = 0; k < 8; k++) a += sm[SM_LS + tid * 8 + k];
            #pragma unroll
            for (int off = 16; off >= 1; off >>= 1)
                a += __shfl_down_sync(0xffffffffu, a, off);
            if (tid == 0) out[BATCH * 256 + b] = a;
        }
    }

    // keep all CTAs resident until every remote store has landed
    asm volatile("barrier.cluster.arrive.aligned;" ::: "memory");
    asm volatile("barrier.cluster.wait.aligned;" ::: "memory");
}

extern "C" void kernel_launch(void* const* d_in, const int* in_sizes, int n_in,
                              void* d_out, int out_size)
{
    (void)in_sizes; (void)n_in; (void)out_size;
    const float* x   = (const float*)d_in[0];
    const float* mw0 = (const float*)d_in[1];
    const float* mb0 = (const float*)d_in[2];
    const float* mw1 = (const float*)d_in[3];
    const float* mb1 = (const float*)d_in[4];
    const float* mw2 = (const float*)d_in[5];
    const float* mb2 = (const float*)d_in[6];
    const float* mwo = (const float*)d_in[7];
    const float* mbo = (const float*)d_in[8];
    const float* lw0 = (const float*)d_in[9];
    const float* lb0 = (const float*)d_in[10];
    const float* lw1 = (const float*)d_in[11];
    const float* lb1 = (const float*)d_in[12];
    const float* lw2 = (const float*)d_in[13];
    const float* lb2 = (const float*)d_in[14];
    const float* lwo = (const float*)d_in[15];
    const float* lbo = (const float*)d_in[16];
    float* out = (float*)d_out;

    cudaFuncSetAttribute(made_kernel, cudaFuncAttributeMaxDynamicSharedMemorySize, SMEM_BYTES);

    repack_kernel<<<(WP_TOTAL + 255) / 256, 256>>>(mw0, mw1, mw2, mwo, lw0, lw1, lw2, lwo);
    made_kernel<<<4 * BATCH, 512, SMEM_BYTES>>>(x, mb0, mb1, mb2, mbo,
                                                lb0, lb1, lb2, lbo, out);
}

// round 9
// speedup vs baseline: 1.6425x; 1.5012x over previous
#include <cuda_runtime.h>
#include <math.h>
#include <stdint.h>

// Problem dims
#define BATCH 32
#define EPS   1e-12f

// ---------------- packed global weight layout (per net, 44800 floats) -------
//  w1 : [tap(5)][o(64)][i(68 pad)]   21760   @ 0
//  w2 : [tap(5)][o(64)][i(68 pad)]   21760   @ 21760
//  w0 : [tap(4)][o(64)][i(4)]         1024   @ 43520
//  wo : [o(64)][ch(4)]                 256   @ 44544
#define NET_STRIDE 44800
#define WP_TOTAL   (2 * NET_STRIDE)

__device__ float g_wp[WP_TOTAL];

// ---------------- shared memory layout (floats) -----------------------------
#define SM_W1    0        // 21760
#define SM_W2    21760    // 21760
#define SM_W0    43520    // 1024
#define SM_WO    44544    // 256
#define SM_H0    44800    // 4096  [64px][64]
#define SM_H1    48896    // 4096
#define SM_RED1  52992    // 1024  [q 4][a 4][o 64]
#define SM_RED2  54016    // 1024
#define SM_Y     55040    // 256   [64px][4ch]
#define SM_X     55296    // 256
#define SM_LS    55552    // 256
#define SM_B0    55808    // 64
#define SM_B1    55872    // 64
#define SM_B2    55936    // 64
#define SM_BO    56000    // 4
#define SM_MLV   56004    // 32    [buf 2][a 4][ch 4]
#define SM_PART  56036    // 32    [a 4][half 2][ch 4]
#define SM_MBAR  56068    // 2     (56068*4 = 224272, 8B aligned)
#define SMEM_FLOATS 56072
#define SMEM_BYTES  (SMEM_FLOATS * 4)

// Mask-A taps (dr,dc): (-1,-1),(-1,0),(-1,1),(0,-1) ; Mask-B: A + center (0,0)
__global__ void repack_kernel(const float* __restrict__ mw0, const float* __restrict__ mw1,
                              const float* __restrict__ mw2, const float* __restrict__ mwo,
                              const float* __restrict__ lw0, const float* __restrict__ lw1,
                              const float* __restrict__ lw2, const float* __restrict__ lwo)
{
    int t = blockIdx.x * blockDim.x + threadIdx.x;
    if (t >= WP_TOTAL) return;
    const int krA[4] = {0,0,0,1}, kcA[4] = {0,1,2,0};
    const int krB[5] = {0,0,0,1,1}, kcB[5] = {0,1,2,0,1};
    int net = t / NET_STRIDE;
    int u   = t % NET_STRIDE;
    float v;
    if (u < 21760) {                       // w1: [tap][o][68]
        int tap = u / 4352, rem = u % 4352;
        int o = rem / 68, i = rem % 68;
        const float* w = net ? lw1 : mw1;
        v = (i < 64) ? w[((o * 64 + i) * 3 + krB[tap]) * 3 + kcB[tap]] : 0.f;
    } else if (u < 43520) {                // w2
        int u2 = u - 21760;
        int tap = u2 / 4352, rem = u2 % 4352;
        int o = rem / 68, i = rem % 68;
        const float* w = net ? lw2 : mw2;
        v = (i < 64) ? w[((o * 64 + i) * 3 + krB[tap]) * 3 + kcB[tap]] : 0.f;
    } else if (u < 44544) {                // w0: [tap][o][4]
        int u2 = u - 43520;
        int tap = u2 / 256, rem = u2 % 256;
        int o = rem / 4, i = rem % 4;
        const float* w = net ? lw0 : mw0;
        v = w[((o * 4 + i) * 3 + krA[tap]) * 3 + kcA[tap]];
    } else {                               // wo: [o][4]
        int u2 = u - 44544;
        int o = u2 / 4, ch = u2 % 4;
        const float* w = net ? lwo : mwo;
        v = w[ch * 64 + o];
    }
    g_wp[t] = v;
}

__device__ __forceinline__ float elu1(float v) {
    return v > 0.f ? v : (__expf(v) - 1.f);
}

__device__ __forceinline__ uint32_t smem_u32(const void* p) {
    uint32_t a;
    asm("{ .reg .u64 t; cvta.to.shared.u64 t, %1; cvt.u32.u64 %0, t; }" : "=r"(a) : "l"(p));
    return a;
}

__device__ __forceinline__ void st_remote_f32(uint32_t saddr, uint32_t rank, float v) {
    uint32_t raddr;
    asm volatile("mapa.shared::cluster.u32 %0, %1, %2;" : "=r"(raddr) : "r"(saddr), "r"(rank));
    asm volatile("st.shared::cluster.f32 [%0], %1;" :: "r"(raddr), "f"(v) : "memory");
}

__device__ __forceinline__ void arrive_remote(uint32_t mbar_saddr, uint32_t rank) {
    asm volatile(
        "{\n\t"
        ".reg .b32 r;\n\t"
        "mapa.shared::cluster.u32 r, %0, %1;\n\t"
        "mbarrier.arrive.release.cluster.shared::cluster.b64 _, [r];\n\t"
        "}"
        :: "r"(mbar_saddr), "r"(rank) : "memory");
}

__device__ __forceinline__ void mbar_wait(uint32_t mbar_saddr, uint32_t parity) {
    asm volatile(
        "{\n\t"
        ".reg .pred P1;\n\t"
        "WAIT_LOOP_%=:\n\t"
        "mbarrier.try_wait.parity.acquire.cluster.shared::cta.b64 P1, [%0], %1, 0x989680;\n\t"
        "@P1 bra.uni WAIT_DONE_%=;\n\t"
        "bra.uni WAIT_LOOP_%=;\n\t"
        "WAIT_DONE_%=:\n\t"
        "}"
        :: "r"(mbar_saddr), "r"(parity) : "memory");
}

#define BAR_SYNC(id, cnt)   asm volatile("bar.sync %0, %1;"   :: "r"(id), "r"(cnt) : "memory")
#define BAR_ARRIVE(id, cnt) asm volatile("bar.arrive %0, %1;" :: "r"(id), "r"(cnt) : "memory")

__global__ void __cluster_dims__(2, 1, 1) __launch_bounds__(512, 1)
made_kernel(const float* __restrict__ x,
            const float* __restrict__ mb0, const float* __restrict__ mb1,
            const float* __restrict__ mb2, const float* __restrict__ mbo,
            const float* __restrict__ lb0, const float* __restrict__ lb1,
            const float* __restrict__ lb2, const float* __restrict__ lbo,
            float* __restrict__ out)
{
    extern __shared__ float sm[];
    const int tid = threadIdx.x;
    const int b = blockIdx.x >> 1;
    uint32_t net;
    asm("mov.u32 %0, %%cluster_ctarank;" : "=r"(net));
    const uint32_t peer = net ^ 1u;
    const uint32_t smbase = smem_u32(sm);
    const uint32_t mbar = smbase + SM_MBAR * 4u;

    // ---- startup: weights + state into smem ----
    {
        const float4* src = (const float4*)(g_wp + net * NET_STRIDE);
        float4* dst = (float4*)sm;
        #pragma unroll 4
        for (int i = tid; i < NET_STRIDE / 4; i += 512)
            dst[i] = src[i];
    }
    if (tid < 256) {
        int ch = tid >> 6, p = tid & 63;
        sm[SM_X + p * 4 + ch] = x[b * 256 + tid];
        sm[SM_Y + tid] = 0.f;
    }
    if (tid < 64) {
        sm[SM_B0 + tid] = net ? lb0[tid] : mb0[tid];
        sm[SM_B1 + tid] = net ? lb1[tid] : mb1[tid];
        sm[SM_B2 + tid] = net ? lb2[tid] : mb2[tid];
    }
    if (tid < 4) sm[SM_BO + tid] = net ? lbo[tid] : mbo[tid];
    if (tid == 0)
        asm volatile("mbarrier.init.shared.b64 [%0], %1;" :: "r"(mbar), "r"(16) : "memory");
    __syncthreads();
    asm volatile("barrier.cluster.arrive.aligned;" ::: "memory");
    asm volatile("barrier.cluster.wait.aligned;" ::: "memory");

    const int dR[4] = {-1,-1,-1, 0}, dC[4] = {-1, 0, 1,-1};  // mask-A = non-center B taps

    if (tid < 256) {
        // ==================== NC warps (0-7): non-center GEMM partials =========
        const int o = tid & 63;
        const int q = tid >> 6;          // 16-float i-quarter
        #pragma unroll 1
        for (int s = 0; s < 22; s++) {
            int rlo = (s - 6) > 0 ? (s - 6) / 2 : 0;
            int rhi = (s >> 1) < 7 ? (s >> 1) : 7;
            int npix = rhi - rlo + 1;
            int ra[4], ca[4];
            #pragma unroll
            for (int a = 0; a < 4; a++) { ra[a] = rlo + a; ca[a] = s - 2 * ra[a]; }

            // ---- GEMM1 non-center partials (reads h0 of older diagonals) ----
            {
                float p0 = 0.f, p1 = 0.f, p2 = 0.f, p3 = 0.f;
                #pragma unroll
                for (int tap = 0; tap < 4; tap++) {
                    const float4* wr = (const float4*)(sm + SM_W1 + (tap * 64 + o) * 68 + q * 16);
                    float4 w0 = wr[0], w1 = wr[1], w2 = wr[2], w3 = wr[3];
                    #pragma unroll
                    for (int a = 0; a < 4; a++) {
                        int rr = ra[a] + dR[tap], cc = ca[a] + dC[tap];
                        if (a < npix && rr >= 0 && cc >= 0 && cc < 8) {
                            const float4* hp = (const float4*)(sm + SM_H0 + (rr * 8 + cc) * 64 + q * 16);
                            float4 h0 = hp[0], h1 = hp[1], h2 = hp[2], h3 = hp[3];
                            float v = w0.x*h0.x + w0.y*h0.y + w0.z*h0.z + w0.w*h0.w
                                    + w1.x*h1.x + w1.y*h1.y + w1.z*h1.z + w1.w*h1.w
                                    + w2.x*h2.x + w2.y*h2.y + w2.z*h2.z + w2.w*h2.w
                                    + w3.x*h3.x + w3.y*h3.y + w3.z*h3.z + w3.w*h3.w;
                            if (a == 0) p0 += v; else if (a == 1) p1 += v;
                            else if (a == 2) p2 += v; else p3 += v;
                        }
                    }
                }
                float* rb = sm + SM_RED1 + q * 256 + o;
                rb[0] = p0; rb[64] = p1; rb[128] = p2; rb[192] = p3;
            }
            BAR_ARRIVE(1, 512);

            // ---- GEMM2 non-center partials (reads h1 of older diagonals) ----
            {
                float p0 = 0.f, p1 = 0.f, p2 = 0.f, p3 = 0.f;
                #pragma unroll
                for (int tap = 0; tap < 4; tap++) {
                    const float4* wr = (const float4*)(sm + SM_W2 + (tap * 64 + o) * 68 + q * 16);
                    float4 w0 = wr[0], w1 = wr[1], w2 = wr[2], w3 = wr[3];
                    #pragma unroll
                    for (int a = 0; a < 4; a++) {
                        int rr = ra[a] + dR[tap], cc = ca[a] + dC[tap];
                        if (a < npix && rr >= 0 && cc >= 0 && cc < 8) {
                            const float4* hp = (const float4*)(sm + SM_H1 + (rr * 8 + cc) * 64 + q * 16);
                            float4 h0 = hp[0], h1 = hp[1], h2 = hp[2], h3 = hp[3];
                            float v = w0.x*h0.x + w0.y*h0.y + w0.z*h0.z + w0.w*h0.w
                                    + w1.x*h1.x + w1.y*h1.y + w1.z*h1.z + w1.w*h1.w
                                    + w2.x*h2.x + w2.y*h2.y + w2.z*h2.z + w2.w*h2.w
                                    + w3.x*h3.x + w3.y*h3.y + w3.z*h3.z + w3.w*h3.w;
                            if (a == 0) p0 += v; else if (a == 1) p1 += v;
                            else if (a == 2) p2 += v; else p3 += v;
                        }
                    }
                }
                float* rb = sm + SM_RED2 + q * 256 + o;
                rb[0] = p0; rb[64] = p1; rb[128] = p2; rb[192] = p3;
            }
            BAR_ARRIVE(2, 512);

            // wait for center to finish consuming RED + publishing h1(s)
            BAR_SYNC(3, 512);
        }
    } else {
        // ==================== CENTER warps (8-15): serial chain ================
        const int t8   = tid - 256;
        const int o    = t8 & 63;
        const int a    = t8 >> 6;                 // pixel slot (warp-uniform)
        const int half = (t8 >> 5) & 1;
        const int lane = tid & 31;
        #pragma unroll 1
        for (int s = 0; s < 22; s++) {
            int rlo = (s - 6) > 0 ? (s - 6) / 2 : 0;
            int rhi = (s >> 1) < 7 ? (s >> 1) : 7;
            int npix = rhi - rlo + 1;
            int ra_ = rlo + a, ca_ = s - 2 * ra_;
            int p = ra_ * 8 + ca_;
            bool valid = (a < npix);
            uint32_t parity = (uint32_t)(s & 1);
            int buf = s & 1;

            // ---- L0 (mask A, 4 -> 64) for my pixel ----
            if (valid) {
                float acc = sm[SM_B0 + o];
                #pragma unroll
                for (int tap = 0; tap < 4; tap++) {
                    int rr = ra_ + dR[tap], cc = ca_ + dC[tap];
                    if (rr >= 0 && cc >= 0 && cc < 8) {
                        float4 w  = *(const float4*)(sm + SM_W0 + (tap * 64 + o) * 4);
                        float4 y4 = *(const float4*)(sm + SM_Y + (rr * 8 + cc) * 4);
                        acc += w.x * y4.x + w.y * y4.y + w.z * y4.z + w.w * y4.w;
                    }
                }
                sm[SM_H0 + p * 64 + o] = elu1(acc);
            }
            BAR_SYNC(1, 512);    // RED1 ready (nc) + h0 visible (center)

            // ---- GEMM1 center tap + combine -> h1 ----
            if (valid) {
                const float4* wr = (const float4*)(sm + SM_W1 + (256 + o) * 68);
                const float4* hp = (const float4*)(sm + SM_H0 + p * 64);
                float s0 = 0.f, s1 = 0.f, s2 = 0.f, s3 = 0.f;
                #pragma unroll
                for (int k = 0; k < 4; k++) {
                    float4 wA = wr[4*k+0], wB = wr[4*k+1], wC = wr[4*k+2], wD = wr[4*k+3];
                    float4 hA = hp[4*k+0], hB = hp[4*k+1], hC = hp[4*k+2], hD = hp[4*k+3];
                    s0 += wA.x*hA.x + wA.y*hA.y + wA.z*hA.z + wA.w*hA.w;
                    s1 += wB.x*hB.x + wB.y*hB.y + wB.z*hB.z + wB.w*hB.w;
                    s2 += wC.x*hC.x + wC.y*hC.y + wC.z*hC.z + wC.w*hC.w;
                    s3 += wD.x*hD.x + wD.y*hD.y + wD.z*hD.z + wD.w*hD.w;
                }
                float v = s0 + s1 + s2 + s3 + sm[SM_B1 + o]
                        + sm[SM_RED1 +   0 + a * 64 + o]
                        + sm[SM_RED1 + 256 + a * 64 + o]
                        + sm[SM_RED1 + 512 + a * 64 + o]
                        + sm[SM_RED1 + 768 + a * 64 + o];
                sm[SM_H1 + p * 64 + o] = elu1(v);
            }
            BAR_SYNC(2, 512);    // RED2 ready (nc) + h1 visible (center)

            // ---- GEMM2 center tap + combine + out conv ----
            float c0 = 0.f, c1 = 0.f, c2 = 0.f, c3 = 0.f;
            if (valid) {
                const float4* wr = (const float4*)(sm + SM_W2 + (256 + o) * 68);
                const float4* hp = (const float4*)(sm + SM_H1 + p * 64);
                float s0 = 0.f, s1 = 0.f, s2 = 0.f, s3 = 0.f;
                #pragma unroll
                for (int k = 0; k < 4; k++) {
                    float4 wA = wr[4*k+0], wB = wr[4*k+1], wC = wr[4*k+2], wD = wr[4*k+3];
                    float4 hA = hp[4*k+0], hB = hp[4*k+1], hC = hp[4*k+2], hD = hp[4*k+3];
                    s0 += wA.x*hA.x + wA.y*hA.y + wA.z*hA.z + wA.w*hA.w;
                    s1 += wB.x*hB.x + wB.y*hB.y + wB.z*hB.z + wB.w*hB.w;
                    s2 += wC.x*hC.x + wC.y*hC.y + wC.z*hC.z + wC.w*hC.w;
                    s3 += wD.x*hD.x + wD.y*hD.y + wD.z*hD.z + wD.w*hD.w;
                }
                float v = s0 + s1 + s2 + s3 + sm[SM_B2 + o]
                        + sm[SM_RED2 +   0 + a * 64 + o]
                        + sm[SM_RED2 + 256 + a * 64 + o]
                        + sm[SM_RED2 + 512 + a * 64 + o]
                        + sm[SM_RED2 + 768 + a * 64 + o];
                v = elu1(v);
                float4 wo4 = *(const float4*)(sm + SM_WO + o * 4);
                c0 = v * wo4.x; c1 = v * wo4.y; c2 = v * wo4.z; c3 = v * wo4.w;
            }
            // release nc warps for step s+1 (h1 published; RED1/RED2 consumed)
            BAR_ARRIVE(3, 512);

            if (valid) {
                #pragma unroll
                for (int off = 16; off >= 1; off >>= 1) {
                    c0 += __shfl_down_sync(0xffffffffu, c0, off);
                    c1 += __shfl_down_sync(0xffffffffu, c1, off);
                    c2 += __shfl_down_sync(0xffffffffu, c2, off);
                    c3 += __shfl_down_sync(0xffffffffu, c3, off);
                }
                if (lane == 0) {
                    float* pp = sm + SM_PART + (a * 2 + half) * 4;
                    pp[0] = c0; pp[1] = c1; pp[2] = c2; pp[3] = c3;
                }
            }
            BAR_SYNC(8, 256);    // center-only: PART visible

            // ---- finalize + peer exchange + y update (t8 < 16) ----
            if (t8 < 16) {
                int aa = t8 >> 2, ch = t8 & 3;
                float v = 0.f;
                if (aa < npix) {
                    v = sm[SM_PART + (aa * 2 + 0) * 4 + ch]
                      + sm[SM_PART + (aa * 2 + 1) * 4 + ch]
                      + sm[SM_BO + ch];
                    uint32_t off = (uint32_t)(SM_MLV + buf * 16 + aa * 4 + ch) * 4u;
                    st_remote_f32(smbase + off, peer, v);
                }
                arrive_remote(mbar, peer);
                mbar_wait(mbar, parity);
                if (aa < npix) {
                    float pv = sm[SM_MLV + buf * 16 + aa * 4 + ch];
                    float mu = net ? pv : v;
                    float ls = 0.5f * (net ? v : pv);
                    int rr2 = rlo + aa;
                    int pp2 = rr2 * 8 + (s - 2 * rr2);
                    float yv = (sm[SM_X + pp2 * 4 + ch] - mu) / (__expf(ls) + EPS);
                    sm[SM_Y + pp2 * 4 + ch] = yv;
                    sm[SM_LS + pp2 * 4 + ch] = ls;
                }
            }
            BAR_SYNC(9, 256);    // center-only: y visible for next L0
        }
    }
    __syncthreads();

    // ---- outputs ----
    if (net == 0) {
        if (tid < 256)
            out[b * 256 + tid] = sm[SM_Y + (tid & 63) * 4 + (tid >> 6)];
    } else {
        if (tid < 32) {
            float a = 0.f;
            #pragma unroll
            for (int k = 0; k < 8; k++) a += sm[SM_LS + tid * 8 + k];
            #pragma unroll
            for (int off = 16; off >= 1; off >>= 1)
                a += __shfl_down_sync(0xffffffffu, a, off);
            if (tid == 0) out[BATCH * 256 + b] = a;
        }
    }

    asm volatile("barrier.cluster.arrive.aligned;" ::: "memory");
    asm volatile("barrier.cluster.wait.aligned;" ::: "memory");
}

extern "C" void kernel_launch(void* const* d_in, const int* in_sizes, int n_in,
                              void* d_out, int out_size)
{
    (void)in_sizes; (void)n_in; (void)out_size;
    const float* x   = (const float*)d_in[0];
    const float* mw0 = (const float*)d_in[1];
    const float* mb0 = (const float*)d_in[2];
    const float* mw1 = (const float*)d_in[3];
    const float* mb1 = (const float*)d_in[4];
    const float* mw2 = (const float*)d_in[5];
    const float* mb2 = (const float*)d_in[6];
    const float* mwo = (const float*)d_in[7];
    const float* mbo = (const float*)d_in[8];
    const float* lw0 = (const float*)d_in[9];
    const float* lb0 = (const float*)d_in[10];
    const float* lw1 = (const float*)d_in[11];
    const float* lb1 = (const float*)d_in[12];
    const float* lw2 = (const float*)d_in[13];
    const float* lb2 = (const float*)d_in[14];
    const float* lwo = (const float*)d_in[15];
    const float* lbo = (const float*)d_in[16];
    float* out = (float*)d_out;

    cudaFuncSetAttribute(made_kernel, cudaFuncAttributeMaxDynamicSharedMemorySize, SMEM_BYTES);

    repack_kernel<<<(WP_TOTAL + 255) / 256, 256>>>(mw0, mw1, mw2, mwo, lw0, lw1, lw2, lwo);
    made_kernel<<<2 * BATCH, 512, SMEM_BYTES>>>(x, mb0, mb1, mb2, mbo,
                                                lb0, lb1, lb2, lbo, out);
}

// round 10
// speedup vs baseline: 1.7014x; 1.0359x over previous
#include <cuda_runtime.h>
#include <math.h>
#include <stdint.h>

// Problem dims
#define BATCH 32
#define EPS   1e-12f

// ---------------- packed global weight layout (per net, 44800 floats) -------
//  w1 : [tap(5)][o(64)][i(68 pad)]   21760   @ 0
//  w2 : [tap(5)][o(64)][i(68 pad)]   21760   @ 21760
//  w0 : [tap(4)][o(64)][i(4)]         1024   @ 43520
//  wo : [o(64)][ch(4)]                 256   @ 44544
#define NET_STRIDE 44800
#define WP_TOTAL   (2 * NET_STRIDE)

__device__ float g_wp[WP_TOTAL];

// ---------------- shared memory layout (floats) -----------------------------
#define SM_W1    0        // 21760
#define SM_W2    21760    // 21760
#define SM_W0    43520    // 1024
#define SM_WO    44544    // 256
#define SM_H0    44800    // 4096  [64px][64]
#define SM_H1    48896    // 4096
#define SM_RED1  52992    // 2048  [buf 2][q 4][a 4][o 64]  (pipelined 1 step ahead)
#define SM_RED2  55040    // 1024  [q 4][a 4][o 64]
#define SM_Y     56064    // 256   [64px][4ch]
#define SM_X     56320    // 256
#define SM_LS    56576    // 256
#define SM_B0    56832    // 64
#define SM_B1    56896    // 64
#define SM_B2    56960    // 64
#define SM_BO    57024    // 4
#define SM_MLV   57028    // 32    [buf 2][a 4][ch 4]
#define SM_PART  57060    // 32    [a 4][half 2][ch 4]
#define SM_MBAR  57092    // 2     (57092*4 = 228368, 8B aligned)
#define SMEM_FLOATS 57096
#define SMEM_BYTES  (SMEM_FLOATS * 4)   // 228384 bytes

// Mask-A taps (dr,dc): (-1,-1),(-1,0),(-1,1),(0,-1) ; Mask-B: A + center (0,0)
__global__ void repack_kernel(const float* __restrict__ mw0, const float* __restrict__ mw1,
                              const float* __restrict__ mw2, const float* __restrict__ mwo,
                              const float* __restrict__ lw0, const float* __restrict__ lw1,
                              const float* __restrict__ lw2, const float* __restrict__ lwo)
{
    int t = blockIdx.x * blockDim.x + threadIdx.x;
    if (t >= WP_TOTAL) return;
    const int krA[4] = {0,0,0,1}, kcA[4] = {0,1,2,0};
    const int krB[5] = {0,0,0,1,1}, kcB[5] = {0,1,2,0,1};
    int net = t / NET_STRIDE;
    int u   = t % NET_STRIDE;
    float v;
    if (u < 21760) {                       // w1: [tap][o][68]
        int tap = u / 4352, rem = u % 4352;
        int o = rem / 68, i = rem % 68;
        const float* w = net ? lw1 : mw1;
        v = (i < 64) ? w[((o * 64 + i) * 3 + krB[tap]) * 3 + kcB[tap]] : 0.f;
    } else if (u < 43520) {                // w2
        int u2 = u - 21760;
        int tap = u2 / 4352, rem = u2 % 4352;
        int o = rem / 68, i = rem % 68;
        const float* w = net ? lw2 : mw2;
        v = (i < 64) ? w[((o * 64 + i) * 3 + krB[tap]) * 3 + kcB[tap]] : 0.f;
    } else if (u < 44544) {                // w0: [tap][o][4]
        int u2 = u - 43520;
        int tap = u2 / 256, rem = u2 % 256;
        int o = rem / 4, i = rem % 4;
        const float* w = net ? lw0 : mw0;
        v = w[((o * 4 + i) * 3 + krA[tap]) * 3 + kcA[tap]];
    } else {                               // wo: [o][4]
        int u2 = u - 44544;
        int o = u2 / 4, ch = u2 % 4;
        const float* w = net ? lwo : mwo;
        v = w[ch * 64 + o];
    }
    g_wp[t] = v;
}

__device__ __forceinline__ float elu1(float v) {
    return v > 0.f ? v : (__expf(v) - 1.f);
}

__device__ __forceinline__ uint32_t smem_u32(const void* p) {
    uint32_t a;
    asm("{ .reg .u64 t; cvta.to.shared.u64 t, %1; cvt.u32.u64 %0, t; }" : "=r"(a) : "l"(p));
    return a;
}

__device__ __forceinline__ void st_remote_f32(uint32_t saddr, uint32_t rank, float v) {
    uint32_t raddr;
    asm volatile("mapa.shared::cluster.u32 %0, %1, %2;" : "=r"(raddr) : "r"(saddr), "r"(rank));
    asm volatile("st.shared::cluster.f32 [%0], %1;" :: "r"(raddr), "f"(v) : "memory");
}

__device__ __forceinline__ void arrive_remote(uint32_t mbar_saddr, uint32_t rank) {
    asm volatile(
        "{\n\t"
        ".reg .b32 r;\n\t"
        "mapa.shared::cluster.u32 r, %0, %1;\n\t"
        "mbarrier.arrive.release.cluster.shared::cluster.b64 _, [r];\n\t"
        "}"
        :: "r"(mbar_saddr), "r"(rank) : "memory");
}

__device__ __forceinline__ void mbar_wait(uint32_t mbar_saddr, uint32_t parity) {
    asm volatile(
        "{\n\t"
        ".reg .pred P1;\n\t"
        "WAIT_LOOP_%=:\n\t"
        "mbarrier.try_wait.parity.acquire.cluster.shared::cta.b64 P1, [%0], %1, 0x989680;\n\t"
        "@P1 bra.uni WAIT_DONE_%=;\n\t"
        "bra.uni WAIT_LOOP_%=;\n\t"
        "WAIT_DONE_%=:\n\t"
        "}"
        :: "r"(mbar_saddr), "r"(parity) : "memory");
}

#define BAR_SYNC(id, cnt)   asm volatile("bar.sync %0, %1;"   :: "r"(id), "r"(cnt) : "memory")
#define BAR_ARRIVE(id, cnt) asm volatile("bar.arrive %0, %1;" :: "r"(id), "r"(cnt) : "memory")

// barrier ids: A=1 (h0 published), B=2 (RED2 ready), C=3 (center2 done: h1 pub + RED2 free),
//              D=4 (RED1 for next step ready), 8/9 center-internal
#define BID_A 1
#define BID_B 2
#define BID_C 3
#define BID_D 4

__global__ void __cluster_dims__(2, 1, 1) __launch_bounds__(512, 1)
made_kernel(const float* __restrict__ x,
            const float* __restrict__ mb0, const float* __restrict__ mb1,
            const float* __restrict__ mb2, const float* __restrict__ mbo,
            const float* __restrict__ lb0, const float* __restrict__ lb1,
            const float* __restrict__ lb2, const float* __restrict__ lbo,
            float* __restrict__ out)
{
    extern __shared__ float sm[];
    const int tid = threadIdx.x;
    const int b = blockIdx.x >> 1;
    uint32_t net;
    asm("mov.u32 %0, %%cluster_ctarank;" : "=r"(net));
    const uint32_t peer = net ^ 1u;
    const uint32_t smbase = smem_u32(sm);
    const uint32_t mbar = smbase + SM_MBAR * 4u;

    // ---- startup: weights + state into smem ----
    {
        const float4* src = (const float4*)(g_wp + net * NET_STRIDE);
        float4* dst = (float4*)sm;
        #pragma unroll 4
        for (int i = tid; i < NET_STRIDE / 4; i += 512)
            dst[i] = src[i];
    }
    if (tid < 256) {
        int ch = tid >> 6, p = tid & 63;
        sm[SM_X + p * 4 + ch] = x[b * 256 + tid];
        sm[SM_Y + tid] = 0.f;
    }
    if (tid < 64) {
        sm[SM_B0 + tid] = net ? lb0[tid] : mb0[tid];
        sm[SM_B1 + tid] = net ? lb1[tid] : mb1[tid];
        sm[SM_B2 + tid] = net ? lb2[tid] : mb2[tid];
    }
    if (tid < 4) sm[SM_BO + tid] = net ? lbo[tid] : mbo[tid];
    if (tid == 0)
        asm volatile("mbarrier.init.shared.b64 [%0], %1;" :: "r"(mbar), "r"(16) : "memory");
    __syncthreads();
    asm volatile("barrier.cluster.arrive.aligned;" ::: "memory");
    asm volatile("barrier.cluster.wait.aligned;" ::: "memory");

    const int dR[4] = {-1,-1,-1, 0}, dC[4] = {-1, 0, 1,-1};  // mask-A = non-center B taps

    if (tid < 256) {
        // ==================== NC warps (0-7): pipelined non-center partials ====
        const int o = tid & 63;
        const int q = tid >> 6;          // 16-float i-quarter

        // ---- prologue: RED1 for step 0 (pixel (0,0) has no valid nc taps) ----
        {
            float* rb = sm + SM_RED1 + q * 256 + o;   // buf 0
            rb[0] = 0.f; rb[64] = 0.f; rb[128] = 0.f; rb[192] = 0.f;
        }
        BAR_ARRIVE(BID_D, 512);

        #pragma unroll 1
        for (int s = 0; s < 22; s++) {
            // ---- GEMM2 non-center partials for step s (h1 of diag <= s-1) ----
            {
                int rlo = (s - 6) > 0 ? (s - 6) / 2 : 0;
                int rhi = (s >> 1) < 7 ? (s >> 1) : 7;
                int npix = rhi - rlo + 1;
                int ra[4], ca[4];
                #pragma unroll
                for (int a = 0; a < 4; a++) { ra[a] = rlo + a; ca[a] = s - 2 * ra[a]; }

                float p0 = 0.f, p1 = 0.f, p2 = 0.f, p3 = 0.f;
                #pragma unroll
                for (int tap = 0; tap < 4; tap++) {
                    const float4* wr = (const float4*)(sm + SM_W2 + (tap * 64 + o) * 68 + q * 16);
                    float4 w0 = wr[0], w1 = wr[1], w2 = wr[2], w3 = wr[3];
                    #pragma unroll
                    for (int a = 0; a < 4; a++) {
                        int rr = ra[a] + dR[tap], cc = ca[a] + dC[tap];
                        if (a < npix && rr >= 0 && cc >= 0 && cc < 8) {
                            const float4* hp = (const float4*)(sm + SM_H1 + (rr * 8 + cc) * 64 + q * 16);
                            float4 h0 = hp[0], h1 = hp[1], h2 = hp[2], h3 = hp[3];
                            float v = w0.x*h0.x + w0.y*h0.y + w0.z*h0.z + w0.w*h0.w
                                    + w1.x*h1.x + w1.y*h1.y + w1.z*h1.z + w1.w*h1.w
                                    + w2.x*h2.x + w2.y*h2.y + w2.z*h2.z + w2.w*h2.w
                                    + w3.x*h3.x + w3.y*h3.y + w3.z*h3.z + w3.w*h3.w;
                            if (a == 0) p0 += v; else if (a == 1) p1 += v;
                            else if (a == 2) p2 += v; else p3 += v;
                        }
                    }
                }
                float* rb = sm + SM_RED2 + q * 256 + o;
                rb[0] = p0; rb[64] = p1; rb[128] = p2; rb[192] = p3;
            }
            BAR_ARRIVE(BID_B, 512);      // RED2(s) ready for center2(s)

            BAR_SYNC(BID_A, 512);        // wait: h0(s) published by center L0(s)

            // ---- GEMM1 non-center partials for step s+1 (h0 of diag <= s) ----
            {
                int t = s + 1;
                int rlo = (t - 6) > 0 ? (t - 6) / 2 : 0;
                int rhi = (t >> 1) < 7 ? (t >> 1) : 7;
                int npix = rhi - rlo + 1;     // 0 when t == 22 (harmless zero-write)
                int ra[4], ca[4];
                #pragma unroll
                for (int a = 0; a < 4; a++) { ra[a] = rlo + a; ca[a] = t - 2 * ra[a]; }

                float p0 = 0.f, p1 = 0.f, p2 = 0.f, p3 = 0.f;
                #pragma unroll
                for (int tap = 0; tap < 4; tap++) {
                    const float4* wr = (const float4*)(sm + SM_W1 + (tap * 64 + o) * 68 + q * 16);
                    float4 w0 = wr[0], w1 = wr[1], w2 = wr[2], w3 = wr[3];
                    #pragma unroll
                    for (int a = 0; a < 4; a++) {
                        int rr = ra[a] + dR[tap], cc = ca[a] + dC[tap];
                        if (a < npix && rr >= 0 && cc >= 0 && cc < 8) {
                            const float4* hp = (const float4*)(sm + SM_H0 + (rr * 8 + cc) * 64 + q * 16);
                            float4 h0 = hp[0], h1 = hp[1], h2 = hp[2], h3 = hp[3];
                            float v = w0.x*h0.x + w0.y*h0.y + w0.z*h0.z + w0.w*h0.w
                                    + w1.x*h1.x + w1.y*h1.y + w1.z*h1.z + w1.w*h1.w
                                    + w2.x*h2.x + w2.y*h2.y + w2.z*h2.z + w2.w*h2.w
                                    + w3.x*h3.x + w3.y*h3.y + w3.z*h3.z + w3.w*h3.w;
                            if (a == 0) p0 += v; else if (a == 1) p1 += v;
                            else if (a == 2) p2 += v; else p3 += v;
                        }
                    }
                }
                float* rb = sm + SM_RED1 + (t & 1) * 1024 + q * 256 + o;
                rb[0] = p0; rb[64] = p1; rb[128] = p2; rb[192] = p3;
            }
            BAR_ARRIVE(BID_D, 512);      // RED1(s+1) ready for center1(s+1)

            BAR_SYNC(BID_C, 512);        // wait: center2(s) done -> h1(s) pub + RED2 free
        }
    } else {
        // ==================== CENTER warps (8-15): serial chain ================
        const int t8   = tid - 256;
        const int o    = t8 & 63;
        const int a    = t8 >> 6;                 // pixel slot (warp-uniform)
        const int half = (t8 >> 5) & 1;
        const int lane = tid & 31;
        #pragma unroll 1
        for (int s = 0; s < 22; s++) {
            int rlo = (s - 6) > 0 ? (s - 6) / 2 : 0;
            int rhi = (s >> 1) < 7 ? (s >> 1) : 7;
            int npix = rhi - rlo + 1;
            int ra_ = rlo + a, ca_ = s - 2 * ra_;
            int p = ra_ * 8 + ca_;
            bool valid = (a < npix);
            uint32_t parity = (uint32_t)(s & 1);
            int buf = s & 1;

            // ---- L0 (mask A, 4 -> 64) for my pixel ----
            if (valid) {
                float acc = sm[SM_B0 + o];
                #pragma unroll
                for (int tap = 0; tap < 4; tap++) {
                    int rr = ra_ + dR[tap], cc = ca_ + dC[tap];
                    if (rr >= 0 && cc >= 0 && cc < 8) {
                        float4 w  = *(const float4*)(sm + SM_W0 + (tap * 64 + o) * 4);
                        float4 y4 = *(const float4*)(sm + SM_Y + (rr * 8 + cc) * 4);
                        acc += w.x * y4.x + w.y * y4.y + w.z * y4.z + w.w * y4.w;
                    }
                }
                sm[SM_H0 + p * 64 + o] = elu1(acc);
            }
            BAR_ARRIVE(BID_A, 512);   // h0(s) published -> nc can start GEMM1nc(s+1)
            BAR_SYNC(BID_D, 512);     // RED1(s) ready (computed last step) + h0 ordering

            // ---- GEMM1 center tap + combine -> h1 ----
            if (valid) {
                const float4* wr = (const float4*)(sm + SM_W1 + (256 + o) * 68);
                const float4* hp = (const float4*)(sm + SM_H0 + p * 64);
                float s0 = 0.f, s1 = 0.f, s2 = 0.f, s3 = 0.f;
                #pragma unroll
                for (int k = 0; k < 4; k++) {
                    float4 wA = wr[4*k+0], wB = wr[4*k+1], wC = wr[4*k+2], wD = wr[4*k+3];
                    float4 hA = hp[4*k+0], hB = hp[4*k+1], hC = hp[4*k+2], hD = hp[4*k+3];
                    s0 += wA.x*hA.x + wA.y*hA.y + wA.z*hA.z + wA.w*hA.w;
                    s1 += wB.x*hB.x + wB.y*hB.y + wB.z*hB.z + wB.w*hB.w;
                    s2 += wC.x*hC.x + wC.y*hC.y + wC.z*hC.z + wC.w*hC.w;
                    s3 += wD.x*hD.x + wD.y*hD.y + wD.z*hD.z + wD.w*hD.w;
                }
                const float* r1 = sm + SM_RED1 + buf * 1024;
                float v = s0 + s1 + s2 + s3 + sm[SM_B1 + o]
                        + r1[  0 + a * 64 + o]
                        + r1[256 + a * 64 + o]
                        + r1[512 + a * 64 + o]
                        + r1[768 + a * 64 + o];
                sm[SM_H1 + p * 64 + o] = elu1(v);
            }
            BAR_SYNC(BID_B, 512);     // RED2(s) ready (nc) + h1 ordering (center)

            // ---- GEMM2 center tap + combine + out conv ----
            float c0 = 0.f, c1 = 0.f, c2 = 0.f, c3 = 0.f;
            if (valid) {
                const float4* wr = (const float4*)(sm + SM_W2 + (256 + o) * 68);
                const float4* hp = (const float4*)(sm + SM_H1 + p * 64);
                float s0 = 0.f, s1 = 0.f, s2 = 0.f, s3 = 0.f;
                #pragma unroll
                for (int k = 0; k < 4; k++) {
                    float4 wA = wr[4*k+0], wB = wr[4*k+1], wC = wr[4*k+2], wD = wr[4*k+3];
                    float4 hA = hp[4*k+0], hB = hp[4*k+1], hC = hp[4*k+2], hD = hp[4*k+3];
                    s0 += wA.x*hA.x + wA.y*hA.y + wA.z*hA.z + wA.w*hA.w;
                    s1 += wB.x*hB.x + wB.y*hB.y + wB.z*hB.z + wB.w*hB.w;
                    s2 += wC.x*hC.x + wC.y*hC.y + wC.z*hC.z + wC.w*hC.w;
                    s3 += wD.x*hD.x + wD.y*hD.y + wD.z*hD.z + wD.w*hD.w;
                }
                float v = s0 + s1 + s2 + s3 + sm[SM_B2 + o]
                        + sm[SM_RED2 +   0 + a * 64 + o]
                        + sm[SM_RED2 + 256 + a * 64 + o]
                        + sm[SM_RED2 + 512 + a * 64 + o]
                        + sm[SM_RED2 + 768 + a * 64 + o];
                v = elu1(v);
                float4 wo4 = *(const float4*)(sm + SM_WO + o * 4);
                c0 = v * wo4.x; c1 = v * wo4.y; c2 = v * wo4.z; c3 = v * wo4.w;
            }
            BAR_ARRIVE(BID_C, 512);   // h1(s) published + RED2 consumed -> nc continues

            if (valid) {
                #pragma unroll
                for (int off = 16; off >= 1; off >>= 1) {
                    c0 += __shfl_down_sync(0xffffffffu, c0, off);
                    c1 += __shfl_down_sync(0xffffffffu, c1, off);
                    c2 += __shfl_down_sync(0xffffffffu, c2, off);
                    c3 += __shfl_down_sync(0xffffffffu, c3, off);
                }
                if (lane == 0) {
                    float* pp = sm + SM_PART + (a * 2 + half) * 4;
                    pp[0] = c0; pp[1] = c1; pp[2] = c2; pp[3] = c3;
                }
            }
            BAR_SYNC(8, 256);    // center-only: PART visible

            // ---- finalize + peer exchange + y update (t8 < 16) ----
            if (t8 < 16) {
                int aa = t8 >> 2, ch = t8 & 3;
                float v = 0.f;
                if (aa < npix) {
                    v = sm[SM_PART + (aa * 2 + 0) * 4 + ch]
                      + sm[SM_PART + (aa * 2 + 1) * 4 + ch]
                      + sm[SM_BO + ch];
                    uint32_t off = (uint32_t)(SM_MLV + buf * 16 + aa * 4 + ch) * 4u;
                    st_remote_f32(smbase + off, peer, v);
                }
                arrive_remote(mbar, peer);
                mbar_wait(mbar, parity);
                if (aa < npix) {
                    float pv = sm[SM_MLV + buf * 16 + aa * 4 + ch];
                    float mu = net ? pv : v;
                    float ls = 0.5f * (net ? v : pv);
                    int rr2 = rlo + aa;
                    int pp2 = rr2 * 8 + (s - 2 * rr2);
                    float yv = (sm[SM_X + pp2 * 4 + ch] - mu) / (__expf(ls) + EPS);
                    sm[SM_Y + pp2 * 4 + ch] = yv;
                    sm[SM_LS + pp2 * 4 + ch] = ls;
                }
            }
            BAR_SYNC(9, 256);    // center-only: y visible for next L0
        }
    }
    __syncthreads();

    // ---- outputs ----
    if (net == 0) {
        if (tid < 256)
            out[b * 256 + tid] = sm[SM_Y + (tid & 63) * 4 + (tid >> 6)];
    } else {
        if (tid < 32) {
            float a = 0.f;
            #pragma unroll
            for (int k = 0; k < 8; k++) a += sm[SM_LS + tid * 8 + k];
            #pragma unroll
            for (int off = 16; off >= 1; off >>= 1)
                a += __shfl_down_sync(0xffffffffu, a, off);
            if (tid == 0) out[BATCH * 256 + b] = a;
        }
    }

    asm volatile("barrier.cluster.arrive.aligned;" ::: "memory");
    asm volatile("barrier.cluster.wait.aligned;" ::: "memory");
}

extern "C" void kernel_launch(void* const* d_in, const int* in_sizes, int n_in,
                              void* d_out, int out_size)
{
    (void)in_sizes; (void)n_in; (void)out_size;
    const float* x   = (const float*)d_in[0];
    const float* mw0 = (const float*)d_in[1];
    const float* mb0 = (const float*)d_in[2];
    const float* mw1 = (const float*)d_in[3];
    const float* mb1 = (const float*)d_in[4];
    const float* mw2 = (const float*)d_in[5];
    const float* mb2 = (const float*)d_in[6];
    const float* mwo = (const float*)d_in[7];
    const float* mbo = (const float*)d_in[8];
    const float* lw0 = (const float*)d_in[9];
    const float* lb0 = (const float*)d_in[10];
    const float* lw1 = (const float*)d_in[11];
    const float* lb1 = (const float*)d_in[12];
    const float* lw2 = (const float*)d_in[13];
    const float* lb2 = (const float*)d_in[14];
    const float* lwo = (const float*)d_in[15];
    const float* lbo = (const float*)d_in[16];
    float* out = (float*)d_out;

    cudaFuncSetAttribute(made_kernel, cudaFuncAttributeMaxDynamicSharedMemorySize, SMEM_BYTES);

    repack_kernel<<<(WP_TOTAL + 255) / 256, 256>>>(mw0, mw1, mw2, mwo, lw0, lw1, lw2, lwo);
    made_kernel<<<2 * BATCH, 512, SMEM_BYTES>>>(x, mb0, mb1, mb2, mbo,
                                                lb0, lb1, lb2, lbo, out);
}